// round 14
// baseline (speedup 1.0000x reference)
#include <cuda_runtime.h>
#include <cuda_bf16.h>
#include <cstdint>

// CollaborativeRNN (GRU-like): B=32, T=256, H=1024, V=10001
// out = [h_final (B*H) | logits (B*T*V)]  (float32)

#define BB 32
#define TT 256
#define HH 1024
#define H2 2048
#define VV 10001
#define NB 128
#define NPAD 10112  // 79 * 128

typedef unsigned long long u64;

// State (row-major [b][k]) and scratch
__device__ float g_h[BB * HH];
__device__ float g_u[BB * HH];
__device__ __align__(16) __nv_bfloat16 g_hhi[BB * HH];
__device__ __align__(16) __nv_bfloat16 g_hlo[BB * HH];
__device__ __align__(16) __nv_bfloat16 g_rhhi[BB * HH];
__device__ __align__(16) __nv_bfloat16 g_rhlo[BB * HH];
__device__ int   g_items[BB * TT];
__device__ int   g_nzodd;
__device__ int   g_count;
__device__ volatile int g_gen;
__device__ __align__(16) __nv_bfloat16 g_Shi[BB * TT * HH];
__device__ __align__(16) __nv_bfloat16 g_Slo[BB * TT * HH];
__device__ __align__(16) __nv_bfloat16 g_WThi[NPAD * HH];   // W_out^T [n][k]
__device__ __align__(16) __nv_bfloat16 g_WTlo[NPAD * HH];

__device__ __forceinline__ uint32_t smem_u32(const void* p) {
    uint32_t a;
    asm("{ .reg .u64 t; cvta.to.shared.u64 t, %1; cvt.u32.u64 %0, t; }"
        : "=r"(a) : "l"(p));
    return a;
}
__device__ __forceinline__ void ldsm_x4(uint32_t* r, uint32_t addr) {
    asm volatile("ldmatrix.sync.aligned.m8n8.x4.shared.b16 {%0,%1,%2,%3}, [%4];"
                 : "=r"(r[0]), "=r"(r[1]), "=r"(r[2]), "=r"(r[3]) : "r"(addr));
}
__device__ __forceinline__ void ldsm_x2(uint32_t* r, uint32_t addr) {
    asm volatile("ldmatrix.sync.aligned.m8n8.x2.shared.b16 {%0,%1}, [%2];"
                 : "=r"(r[0]), "=r"(r[1]) : "r"(addr));
}
__device__ __forceinline__ void mma16816(float* c, const uint32_t* a,
                                         const uint32_t* b) {
    asm volatile(
        "mma.sync.aligned.m16n8k16.row.col.f32.bf16.bf16.f32 "
        "{%0,%1,%2,%3}, {%4,%5,%6,%7}, {%8,%9}, {%0,%1,%2,%3};"
        : "+f"(c[0]), "+f"(c[1]), "+f"(c[2]), "+f"(c[3])
        : "r"(a[0]), "r"(a[1]), "r"(a[2]), "r"(a[3]), "r"(b[0]), "r"(b[1]));
}
__device__ __forceinline__ void stg16(__nv_bfloat16* p, __nv_bfloat16 v) {
    unsigned short u = *(unsigned short*)&v;
    asm volatile("st.global.cg.u16 [%0], %1;" :: "l"(p), "h"(u));
}
__device__ __forceinline__ void cp16(uint32_t saddr, const void* g) {
    asm volatile("cp.async.cg.shared.global [%0], [%1], 16;"
                 :: "r"(saddr), "l"(g));
}
#define CP_COMMIT() asm volatile("cp.async.commit_group;" ::: "memory")
#define CP_WAIT0()  asm volatile("cp.async.wait_group 0;" ::: "memory")

// ---------------------------------------------------------------------------
__global__ void k_init(const float* __restrict__ h0) {
    int i = blockIdx.x * blockDim.x + threadIdx.x;
    if (i == 0) { g_nzodd = 0; g_count = 0; g_gen = 0; }
    if (i < BB * HH) {
        float x = h0[i];
        g_h[i] = x;
        __nv_bfloat16 hi = __float2bfloat16(x);
        g_hhi[i] = hi;
        g_hlo[i] = __float2bfloat16(x - __bfloat162float(hi));
    }
}
__global__ void k_detect(const int* __restrict__ w) {
    int i = blockIdx.x * blockDim.x + threadIdx.x;
    if (i < (BB * TT) / 2) {
        if (w[2 * i + 1] != 0) atomicOr(&g_nzodd, 1);
    }
}
__global__ void k_convert(const int* __restrict__ w) {
    int i = blockIdx.x * blockDim.x + threadIdx.x;
    if (i < BB * TT) g_items[i] = g_nzodd ? w[i] : w[2 * i];
}

// ---------------------------------------------------------------------------
__device__ __forceinline__ void gridbar() {
    __syncthreads();
    if (threadIdx.x == 0) {
        __threadfence();
        int gen = g_gen;
        if (atomicAdd(&g_count, 1) == NB - 1) {
            atomicExch(&g_count, 0);
            __threadfence();
            g_gen = gen + 1;
        } else {
            while (g_gen == gen) { __nanosleep(64); }
            __threadfence();
        }
    }
    __syncthreads();
}

// ---------------------------------------------------------------------------
// Tensor-core persistent recurrence, cp.async double-buffered staging.
// 128 blocks x 512 threads (16 warps).
#define RSW 1032   // W row stride (bf16 elements)
#define RSH 264    // h stage row stride (bf16 elements); 528 B
#define SM_WRUHI 0
#define SM_WRULO 33024
#define SM_WCHI  66048
#define SM_WCLO  82560
#define SM_STG   99072     // 2 buffers x 33792 B (hi at +0, lo at +16896)
#define STGSZ    33792
#define SM_RED   166656    // 32768 B
#define SM_TOTAL 199424

__global__ __launch_bounds__(512) void k_rnn(
    const float* __restrict__ Eru, const float* __restrict__ bru,
    const float* __restrict__ Ec,  const float* __restrict__ bc,
    const float* __restrict__ Wru, const float* __restrict__ Wc)
{
    extern __shared__ char sm[];
    const uint32_t sb = smem_u32(sm);
    float* red = (float*)(sm + SM_RED);

    const int tid  = threadIdx.x;
    const int lane = tid & 31;
    const int wid  = tid >> 5;
    const int blk  = blockIdx.x;

    // One-time weight load + split conversion into smem
    for (int j = 0; j < 32; j++) {
        int i = tid + j * 512;               // 0..16383
        int n = i & 15, k = i >> 4;
        float x = Wru[k * H2 + blk * 16 + n];
        __nv_bfloat16 hi = __float2bfloat16(x);
        *(__nv_bfloat16*)(sm + SM_WRUHI + (n * RSW + k) * 2) = hi;
        *(__nv_bfloat16*)(sm + SM_WRULO + (n * RSW + k) * 2) =
            __float2bfloat16(x - __bfloat162float(hi));
    }
    for (int j = 0; j < 16; j++) {
        int i = tid + j * 512;               // 0..8191
        int n = i & 7, k = i >> 3;
        float x = Wc[k * HH + blk * 8 + n];
        __nv_bfloat16 hi = __float2bfloat16(x);
        *(__nv_bfloat16*)(sm + SM_WCHI + (n * RSW + k) * 2) = hi;
        *(__nv_bfloat16*)(sm + SM_WCLO + (n * RSW + k) * 2) =
            __float2bfloat16(x - __bfloat162float(hi));
    }

    // Output roles
    const int mA = tid >> 4, nA = tid & 15;       // phase A (512 outputs)
    const int colA = blk * 16 + nA;
    const float bAv = bru[colA];
    const int mB = tid >> 3, nB = tid & 7;        // phase B (256 outputs)
    const int colB = blk * 8 + nB;
    const float bBv = (tid < 256) ? bc[colB] : 0.f;

    // ldmatrix lane addressing (validated mapping)
    const int lm_mat = lane >> 3, lm_r = lane & 7;
    const int a_row_add = lm_r + ((lm_mat & 1) << 3);
    const int a_k_add   = (lm_mat >> 1) << 3;
    const int b_row_add = lm_r + ((lm_mat >> 1) << 3);
    const int b_k_add   = (lm_mat & 1) << 3;
    const int l16 = lane & 15;
    const int c_row = l16 & 7, c_k_add = (l16 >> 3) << 3;

    // Staging thread map (constant across chunks)
    const int s_mm0 = tid >> 5,        s_q0 = tid & 31;         // idx = tid
    const int s_mm1 = (tid + 512) >> 5, s_q1 = tid & 31;        // idx = tid+512

    __syncthreads();

    for (int t = 0; t < TT; t++) {
        // ================= Phase A: ru gates =================
        float eA = Eru[g_items[mA * TT + t] * H2 + colA];
        float accA[2][2][4];
#pragma unroll
        for (int mi = 0; mi < 2; mi++)
#pragma unroll
            for (int ni = 0; ni < 2; ni++)
#pragma unroll
                for (int q = 0; q < 4; q++) accA[mi][ni][q] = 0.f;

        // prefetch chunk 0
        {
            uint32_t base = sb + SM_STG;
            cp16(base + s_mm0 * (RSH * 2) + s_q0 * 16,
                 g_hhi + s_mm0 * HH + s_q0 * 8);
            cp16(base + 16896 + s_mm0 * (RSH * 2) + s_q0 * 16,
                 g_hlo + s_mm0 * HH + s_q0 * 8);
            cp16(base + s_mm1 * (RSH * 2) + s_q1 * 16,
                 g_hhi + s_mm1 * HH + s_q1 * 8);
            cp16(base + 16896 + s_mm1 * (RSH * 2) + s_q1 * 16,
                 g_hlo + s_mm1 * HH + s_q1 * 8);
            CP_COMMIT();
        }
#pragma unroll
        for (int c = 0; c < 4; c++) {
            CP_WAIT0();
            __syncthreads();
            if (c + 1 < 4) {
                uint32_t base = sb + SM_STG + ((c + 1) & 1) * STGSZ;
                const int ko = (c + 1) * 256;
                cp16(base + s_mm0 * (RSH * 2) + s_q0 * 16,
                     g_hhi + s_mm0 * HH + ko + s_q0 * 8);
                cp16(base + 16896 + s_mm0 * (RSH * 2) + s_q0 * 16,
                     g_hlo + s_mm0 * HH + ko + s_q0 * 8);
                cp16(base + s_mm1 * (RSH * 2) + s_q1 * 16,
                     g_hhi + s_mm1 * HH + ko + s_q1 * 8);
                cp16(base + 16896 + s_mm1 * (RSH * 2) + s_q1 * 16,
                     g_hlo + s_mm1 * HH + ko + s_q1 * 8);
                CP_COMMIT();
            }
            const uint32_t stg = sb + SM_STG + (c & 1) * STGSZ;
            const int kk = wid * 16;          // k within chunk
            const int kg = c * 256 + kk;      // global k (for W)
            uint32_t ahi[2][4], alo[2][4], bh[4], bl[4];
#pragma unroll
            for (int mi = 0; mi < 2; mi++) {
                uint32_t off = (uint32_t)((mi * 16 + a_row_add) * (RSH * 2) +
                                          (kk + a_k_add) * 2);
                ldsm_x4(ahi[mi], stg + off);
                ldsm_x4(alo[mi], stg + 16896 + off);
            }
            {
                uint32_t off = (uint32_t)(b_row_add * (RSW * 2) +
                                          (kg + b_k_add) * 2);
                ldsm_x4(bh, sb + SM_WRUHI + off);
                ldsm_x4(bl, sb + SM_WRULO + off);
            }
#pragma unroll
            for (int mi = 0; mi < 2; mi++)
#pragma unroll
                for (int ni = 0; ni < 2; ni++) {
                    mma16816(accA[mi][ni], ahi[mi], &bh[ni * 2]);
                    mma16816(accA[mi][ni], ahi[mi], &bl[ni * 2]);
                    mma16816(accA[mi][ni], alo[mi], &bh[ni * 2]);
                }
        }
        __syncthreads();
#pragma unroll
        for (int mi = 0; mi < 2; mi++)
#pragma unroll
            for (int ni = 0; ni < 2; ni++)
                *(float4*)(red + (wid * 4 + mi * 2 + ni) * 128 + lane * 4) =
                    make_float4(accA[mi][ni][0], accA[mi][ni][1],
                                accA[mi][ni][2], accA[mi][ni][3]);
        __syncthreads();
        {
            int mi = mA >> 4, rm = mA & 15, ni = nA >> 3;
            int rl = ((rm & 7) << 2) | ((nA & 7) >> 1);
            int rg = ((rm >> 3) << 1) | (nA & 1);
            float s = eA + bAv;
            const float* rp = red + (mi * 2 + ni) * 128 + rl * 4 + rg;
#pragma unroll
            for (int w = 0; w < 16; w++) s += rp[w * 512];
            float p = 1.f / (1.f + __expf(-s));
            if (blk < 64) {              // r gate -> rh split bf16
                float h = __ldcg(&g_h[mA * HH + colA]);
                float rh = p * h;
                __nv_bfloat16 hi = __float2bfloat16(rh);
                stg16(&g_rhhi[mA * HH + colA], hi);
                stg16(&g_rhlo[mA * HH + colA],
                      __float2bfloat16(rh - __bfloat162float(hi)));
            } else {                     // u gate
                __stcg(&g_u[mA * HH + (colA - HH)], p);
            }
        }
        // Prefetch phase-B embedding (independent of barrier)
        float eB = 0.f;
        if (tid < 256) eB = Ec[g_items[mB * TT + t] * HH + colB];
        gridbar();

        // ================= Phase B: candidate + h update =================
        float accB[2][4];
#pragma unroll
        for (int mi = 0; mi < 2; mi++)
#pragma unroll
            for (int q = 0; q < 4; q++) accB[mi][q] = 0.f;

        {
            uint32_t base = sb + SM_STG;
            cp16(base + s_mm0 * (RSH * 2) + s_q0 * 16,
                 g_rhhi + s_mm0 * HH + s_q0 * 8);
            cp16(base + 16896 + s_mm0 * (RSH * 2) + s_q0 * 16,
                 g_rhlo + s_mm0 * HH + s_q0 * 8);
            cp16(base + s_mm1 * (RSH * 2) + s_q1 * 16,
                 g_rhhi + s_mm1 * HH + s_q1 * 8);
            cp16(base + 16896 + s_mm1 * (RSH * 2) + s_q1 * 16,
                 g_rhlo + s_mm1 * HH + s_q1 * 8);
            CP_COMMIT();
        }
#pragma unroll
        for (int c = 0; c < 4; c++) {
            CP_WAIT0();
            __syncthreads();
            if (c + 1 < 4) {
                uint32_t base = sb + SM_STG + ((c + 1) & 1) * STGSZ;
                const int ko = (c + 1) * 256;
                cp16(base + s_mm0 * (RSH * 2) + s_q0 * 16,
                     g_rhhi + s_mm0 * HH + ko + s_q0 * 8);
                cp16(base + 16896 + s_mm0 * (RSH * 2) + s_q0 * 16,
                     g_rhlo + s_mm0 * HH + ko + s_q0 * 8);
                cp16(base + s_mm1 * (RSH * 2) + s_q1 * 16,
                     g_rhhi + s_mm1 * HH + ko + s_q1 * 8);
                cp16(base + 16896 + s_mm1 * (RSH * 2) + s_q1 * 16,
                     g_rhlo + s_mm1 * HH + ko + s_q1 * 8);
                CP_COMMIT();
            }
            const uint32_t stg = sb + SM_STG + (c & 1) * STGSZ;
            const int kk = wid * 16;
            const int kg = c * 256 + kk;
            uint32_t ahi[2][4], alo[2][4], bh2[2], bl2[2];
#pragma unroll
            for (int mi = 0; mi < 2; mi++) {
                uint32_t off = (uint32_t)((mi * 16 + a_row_add) * (RSH * 2) +
                                          (kk + a_k_add) * 2);
                ldsm_x4(ahi[mi], stg + off);
                ldsm_x4(alo[mi], stg + 16896 + off);
            }
            {
                uint32_t off = (uint32_t)(c_row * (RSW * 2) +
                                          (kg + c_k_add) * 2);
                ldsm_x2(bh2, sb + SM_WCHI + off);
                ldsm_x2(bl2, sb + SM_WCLO + off);
            }
#pragma unroll
            for (int mi = 0; mi < 2; mi++) {
                mma16816(accB[mi], ahi[mi], bh2);
                mma16816(accB[mi], ahi[mi], bl2);
                mma16816(accB[mi], alo[mi], bh2);
            }
        }
        __syncthreads();
#pragma unroll
        for (int mi = 0; mi < 2; mi++)
            *(float4*)(red + (wid * 2 + mi) * 128 + lane * 4) =
                make_float4(accB[mi][0], accB[mi][1], accB[mi][2], accB[mi][3]);
        __syncthreads();
        if (tid < 256) {
            int mi = mB >> 4, rm = mB & 15;
            int rl = ((rm & 7) << 2) | (nB >> 1);
            int rg = ((rm >> 3) << 1) | (nB & 1);
            float s = eB + bBv;
            const float* rp = red + mi * 128 + rl * 4 + rg;
#pragma unroll
            for (int w = 0; w < 16; w++) s += rp[w * 256];
            float cc = tanhf(s);
            float u = __ldcg(&g_u[mB * HH + colB]);
            float h = __ldcg(&g_h[mB * HH + colB]);
            float hn = u * h + (1.f - u) * cc;
            __stcg(&g_h[mB * HH + colB], hn);
            __nv_bfloat16 hi = __float2bfloat16(hn);
            __nv_bfloat16 lo = __float2bfloat16(hn - __bfloat162float(hi));
            stg16(&g_hhi[mB * HH + colB], hi);
            stg16(&g_hlo[mB * HH + colB], lo);
            stg16(&g_Shi[(mB * TT + t) * HH + colB], hi);
            stg16(&g_Slo[(mB * TT + t) * HH + colB], lo);
        }
        gridbar();
    }
}

// ---------------------------------------------------------------------------
__global__ void k_conv_w(const float* __restrict__ Wo) {
    int i = blockIdx.x * blockDim.x + threadIdx.x;
    if (i < NPAD * HH) {
        int n = i >> 10, k = i & 1023;
        float x = (n < VV) ? Wo[k * VV + n] : 0.0f;
        __nv_bfloat16 hi = __float2bfloat16(x);
        g_WThi[n * HH + k] = hi;
        g_WTlo[n * HH + k] = __float2bfloat16(x - __bfloat162float(hi));
    }
}

// ---------------------------------------------------------------------------
// Tensor-core output GEMM with cp.async double buffering.
// C[8192, V] = S @ Wo.  Split bf16: D = Shi*Bhi + Shi*Blo + Slo*Bhi.
#define RSB 80      // smem row stride bytes (40 bf16)
#define GBUF 40960  // per-stage buffer (4 tiles x 10240)

__global__ __launch_bounds__(256) void k_gemm_tc(float* __restrict__ C) {
    extern __shared__ __align__(16) char smg[];
    const uint32_t sbase = smem_u32(smg);

    const int tid = threadIdx.x, lane = tid & 31, wid = tid >> 5;
    const int warp_m = wid >> 2, warp_n = wid & 3;   // 2 x 4
    const int mt = blockIdx.x * 128, nt = blockIdx.y * 128;

    float acc[4][4][4];
#pragma unroll
    for (int mi = 0; mi < 4; mi++)
#pragma unroll
        for (int ni = 0; ni < 4; ni++)
#pragma unroll
            for (int q = 0; q < 4; q++) acc[mi][ni][q] = 0.f;

    const int lm_mat = lane >> 3, lm_r = lane & 7;
    const int a_row_add = lm_r + ((lm_mat & 1) << 3);
    const int a_k_add   = (lm_mat >> 1) << 3;
    const int b_row_add = lm_r + ((lm_mat >> 1) << 3);
    const int b_k_add   = (lm_mat & 1) << 3;

    // staging issue for chunk ch into buffer buf
    auto issue = [&](int ch, int buf) {
        const int k0 = ch * 32;
        uint32_t base = sbase + buf * GBUF;
#pragma unroll
        for (int j = 0; j < 8; j++) {
            int idx = tid + j * 256;
            int tile = idx >> 9;
            int e = idx & 511;
            int r = e >> 2, q = e & 3;
            uint32_t dst = base + tile * 10240 + r * RSB + q * 16;
            const __nv_bfloat16* src;
            if (tile == 0)      src = &g_Shi[(mt + r) * HH + k0 + q * 8];
            else if (tile == 1) src = &g_Slo[(mt + r) * HH + k0 + q * 8];
            else if (tile == 2) src = &g_WThi[(nt + r) * HH + k0 + q * 8];
            else                src = &g_WTlo[(nt + r) * HH + k0 + q * 8];
            cp16(dst, src);
        }
        CP_COMMIT();
    };

    issue(0, 0);
    for (int ch = 0; ch < 32; ch++) {
        CP_WAIT0();
        __syncthreads();
        if (ch + 1 < 32) issue(ch + 1, (ch + 1) & 1);
        const uint32_t bs = sbase + (ch & 1) * GBUF;
        const uint32_t sAhi = bs, sAlo = bs + 10240;
        const uint32_t sBhi = bs + 20480, sBlo = bs + 30720;

#pragma unroll
        for (int kk = 0; kk < 32; kk += 16) {
            uint32_t ahi[4][4], alo[4][4], bhi[2][4], blo[2][4];
#pragma unroll
            for (int mi = 0; mi < 4; mi++) {
                int row = warp_m * 64 + mi * 16 + a_row_add;
                uint32_t off = (uint32_t)(row * RSB + (kk + a_k_add) * 2);
                ldsm_x4(ahi[mi], sAhi + off);
                ldsm_x4(alo[mi], sAlo + off);
            }
#pragma unroll
            for (int p = 0; p < 2; p++) {
                int row = warp_n * 32 + p * 16 + b_row_add;
                uint32_t off = (uint32_t)(row * RSB + (kk + b_k_add) * 2);
                ldsm_x4(bhi[p], sBhi + off);
                ldsm_x4(blo[p], sBlo + off);
            }
#pragma unroll
            for (int mi = 0; mi < 4; mi++)
#pragma unroll
                for (int ni = 0; ni < 4; ni++) {
                    const uint32_t* bh = &bhi[ni >> 1][(ni & 1) * 2];
                    const uint32_t* bl = &blo[ni >> 1][(ni & 1) * 2];
                    mma16816(acc[mi][ni], ahi[mi], bh);
                    mma16816(acc[mi][ni], ahi[mi], bl);
                    mma16816(acc[mi][ni], alo[mi], bh);
                }
        }
        __syncthreads();
    }

    const int g = lane >> 2, t2 = (lane & 3) * 2;
#pragma unroll
    for (int mi = 0; mi < 4; mi++) {
#pragma unroll
        for (int ni = 0; ni < 4; ni++) {
            int m0 = mt + warp_m * 64 + mi * 16 + g;
            int n0 = nt + warp_n * 32 + ni * 8 + t2;
            if (n0 < VV) {
                C[m0 * VV + n0] = acc[mi][ni][0];
                C[(m0 + 8) * VV + n0] = acc[mi][ni][2];
            }
            if (n0 + 1 < VV) {
                C[m0 * VV + n0 + 1] = acc[mi][ni][1];
                C[(m0 + 8) * VV + n0 + 1] = acc[mi][ni][3];
            }
        }
    }
}

// ---------------------------------------------------------------------------
__global__ void k_hfinal(float* __restrict__ out) {
    int i = blockIdx.x * blockDim.x + threadIdx.x;
    if (i < BB * HH) out[i] = g_h[i];
}

// ---------------------------------------------------------------------------
extern "C" void kernel_launch(void* const* d_in, const int* in_sizes, int n_in,
                              void* d_out, int out_size)
{
    const int*   items_raw = (const int*)d_in[0];
    const float* h0   = (const float*)d_in[1];
    const float* E_ru = (const float*)d_in[2];
    const float* W_ru = (const float*)d_in[3];
    const float* b_ru = (const float*)d_in[4];
    const float* E_c  = (const float*)d_in[5];
    const float* W_c  = (const float*)d_in[6];
    const float* b_c  = (const float*)d_in[7];
    const float* W_out = (const float*)d_in[8];

    float* out = (float*)d_out;
    float* logits = out + BB * HH;

    cudaFuncSetAttribute(k_rnn, cudaFuncAttributeMaxDynamicSharedMemorySize,
                         SM_TOTAL);
    cudaFuncSetAttribute(k_gemm_tc, cudaFuncAttributeMaxDynamicSharedMemorySize,
                         2 * GBUF);

    k_init<<<(BB * HH + 255) / 256, 256>>>(h0);
    k_detect<<<(BB * TT / 2 + 255) / 256, 256>>>(items_raw);
    k_convert<<<(BB * TT + 255) / 256, 256>>>(items_raw);
    k_conv_w<<<(NPAD * HH + 255) / 256, 256>>>(W_out);

    k_rnn<<<NB, 512, SM_TOTAL>>>(E_ru, b_ru, E_c, b_c, W_ru, W_c);

    dim3 ggrid((BB * TT) / 128, NPAD / 128);
    k_gemm_tc<<<ggrid, 256, 2 * GBUF>>>(logits);

    k_hfinal<<<(BB * HH + 255) / 256, 256>>>(out);
}

// round 15
// speedup vs baseline: 1.0546x; 1.0546x over previous
#include <cuda_runtime.h>
#include <cuda_bf16.h>
#include <cstdint>

// CollaborativeRNN (GRU-like): B=32, T=256, H=1024, V=10001
// out = [h_final (B*H) | logits (B*T*V)]  (float32)

#define BB 32
#define TT 256
#define HH 1024
#define H2 2048
#define VV 10001
#define NB 128
#define NPAD 10112  // 79 * 128

typedef unsigned long long u64;

// State (row-major [b][k]) and scratch
__device__ float g_h[BB * HH];
__device__ float g_u[BB * HH];
__device__ __align__(16) __nv_bfloat16 g_hhi[BB * HH];
__device__ __align__(16) __nv_bfloat16 g_hlo[BB * HH];
__device__ __align__(16) __nv_bfloat16 g_rhhi[BB * HH];
__device__ __align__(16) __nv_bfloat16 g_rhlo[BB * HH];
__device__ int   g_items[BB * TT];
__device__ int   g_nzodd;
__device__ int   g_count;
__device__ volatile int g_gen;
__device__ int   g_cnt_rh;
__device__ int   g_cnt_u;
__device__ volatile int g_gen_rh;
__device__ volatile int g_gen_u;
__device__ __align__(16) __nv_bfloat16 g_Shi[BB * TT * HH];
__device__ __align__(16) __nv_bfloat16 g_Slo[BB * TT * HH];
__device__ __align__(16) __nv_bfloat16 g_WThi[NPAD * HH];   // W_out^T [n][k]
__device__ __align__(16) __nv_bfloat16 g_WTlo[NPAD * HH];

__device__ __forceinline__ uint32_t smem_u32(const void* p) {
    uint32_t a;
    asm("{ .reg .u64 t; cvta.to.shared.u64 t, %1; cvt.u32.u64 %0, t; }"
        : "=r"(a) : "l"(p));
    return a;
}
__device__ __forceinline__ void ldsm_x4(uint32_t* r, uint32_t addr) {
    asm volatile("ldmatrix.sync.aligned.m8n8.x4.shared.b16 {%0,%1,%2,%3}, [%4];"
                 : "=r"(r[0]), "=r"(r[1]), "=r"(r[2]), "=r"(r[3]) : "r"(addr));
}
__device__ __forceinline__ void ldsm_x2(uint32_t* r, uint32_t addr) {
    asm volatile("ldmatrix.sync.aligned.m8n8.x2.shared.b16 {%0,%1}, [%2];"
                 : "=r"(r[0]), "=r"(r[1]) : "r"(addr));
}
__device__ __forceinline__ void mma16816(float* c, const uint32_t* a,
                                         const uint32_t* b) {
    asm volatile(
        "mma.sync.aligned.m16n8k16.row.col.f32.bf16.bf16.f32 "
        "{%0,%1,%2,%3}, {%4,%5,%6,%7}, {%8,%9}, {%0,%1,%2,%3};"
        : "+f"(c[0]), "+f"(c[1]), "+f"(c[2]), "+f"(c[3])
        : "r"(a[0]), "r"(a[1]), "r"(a[2]), "r"(a[3]), "r"(b[0]), "r"(b[1]));
}
__device__ __forceinline__ void stg16(__nv_bfloat16* p, __nv_bfloat16 v) {
    unsigned short u = *(unsigned short*)&v;
    asm volatile("st.global.cg.u16 [%0], %1;" :: "l"(p), "h"(u));
}

// ---------------------------------------------------------------------------
__global__ void k_init(const float* __restrict__ h0) {
    int i = blockIdx.x * blockDim.x + threadIdx.x;
    if (i == 0) {
        g_nzodd = 0; g_count = 0; g_gen = 0;
        g_cnt_rh = 0; g_cnt_u = 0; g_gen_rh = 0; g_gen_u = 0;
    }
    if (i < BB * HH) {
        float x = h0[i];
        g_h[i] = x;
        __nv_bfloat16 hi = __float2bfloat16(x);
        g_hhi[i] = hi;
        g_hlo[i] = __float2bfloat16(x - __bfloat162float(hi));
    }
}
__global__ void k_detect(const int* __restrict__ w) {
    int i = blockIdx.x * blockDim.x + threadIdx.x;
    if (i < (BB * TT) / 2) {
        if (w[2 * i + 1] != 0) atomicOr(&g_nzodd, 1);
    }
}
__global__ void k_convert(const int* __restrict__ w) {
    int i = blockIdx.x * blockDim.x + threadIdx.x;
    if (i < BB * TT) g_items[i] = g_nzodd ? w[i] : w[2 * i];
}

// ---------------------------------------------------------------------------
// Full end-of-step grid barrier
__device__ __forceinline__ void gridbar() {
    __syncthreads();
    if (threadIdx.x == 0) {
        __threadfence();
        int gen = g_gen;
        if (atomicAdd(&g_count, 1) == NB - 1) {
            atomicExch(&g_count, 0);
            __threadfence();
            g_gen = gen + 1;
        } else {
            while (g_gen == gen) { __nanosleep(32); }
            __threadfence();
        }
    }
    __syncthreads();
}

// ---------------------------------------------------------------------------
// Tensor-core persistent recurrence (R13 staging, split mid-step barrier,
// hoisted epilogue operands, fused h_final). 128 blocks x 512 threads.
#define RSW 1032   // W row stride (bf16 elements)
#define RSH 264    // h stage row stride (bf16 elements)
#define SM_WRUHI 0
#define SM_WRULO 33024
#define SM_WCHI  66048
#define SM_WCLO  82560
#define SM_HHI   99072
#define SM_HLO   115968
#define SM_RED   132864
#define SM_TOTAL 165632

__global__ __launch_bounds__(512) void k_rnn(
    const float* __restrict__ Eru, const float* __restrict__ bru,
    const float* __restrict__ Ec,  const float* __restrict__ bc,
    const float* __restrict__ Wru, const float* __restrict__ Wc,
    float* __restrict__ hf_out)
{
    extern __shared__ char sm[];
    const uint32_t sb = smem_u32(sm);
    float* red = (float*)(sm + SM_RED);

    const int tid  = threadIdx.x;
    const int lane = tid & 31;
    const int wid  = tid >> 5;
    const int blk  = blockIdx.x;

    // One-time weight load + split conversion into smem
    for (int j = 0; j < 32; j++) {
        int i = tid + j * 512;               // 0..16383
        int n = i & 15, k = i >> 4;
        float x = Wru[k * H2 + blk * 16 + n];
        __nv_bfloat16 hi = __float2bfloat16(x);
        *(__nv_bfloat16*)(sm + SM_WRUHI + (n * RSW + k) * 2) = hi;
        *(__nv_bfloat16*)(sm + SM_WRULO + (n * RSW + k) * 2) =
            __float2bfloat16(x - __bfloat162float(hi));
    }
    for (int j = 0; j < 16; j++) {
        int i = tid + j * 512;               // 0..8191
        int n = i & 7, k = i >> 3;
        float x = Wc[k * HH + blk * 8 + n];
        __nv_bfloat16 hi = __float2bfloat16(x);
        *(__nv_bfloat16*)(sm + SM_WCHI + (n * RSW + k) * 2) = hi;
        *(__nv_bfloat16*)(sm + SM_WCLO + (n * RSW + k) * 2) =
            __float2bfloat16(x - __bfloat162float(hi));
    }

    // Output roles
    const int mA = tid >> 4, nA = tid & 15;       // phase A (512 outputs)
    const int colA = blk * 16 + nA;
    const float bAv = bru[colA];
    const int mB = tid >> 3, nB = tid & 7;        // phase B (256 outputs)
    const int colB = blk * 8 + nB;
    const float bBv = (tid < 256) ? bc[colB] : 0.f;

    // ldmatrix lane addressing (validated mapping)
    const int lm_mat = lane >> 3, lm_r = lane & 7;
    const int a_row_add = lm_r + ((lm_mat & 1) << 3);
    const int a_k_add   = (lm_mat >> 1) << 3;
    const int b_row_add = lm_r + ((lm_mat >> 1) << 3);
    const int b_k_add   = (lm_mat & 1) << 3;
    const int l16 = lane & 15;
    const int c_row = l16 & 7, c_k_add = (l16 >> 3) << 3;

    __syncthreads();

    for (int t = 0; t < TT; t++) {
        // ================= Phase A: ru gates =================
        float eA = Eru[g_items[mA * TT + t] * H2 + colA];
        // Hoisted epilogue operand: h is stable for the whole step.
        float hA = 0.f;
        if (blk < 64) hA = __ldcg(&g_h[mA * HH + colA]);

        float accA[2][2][4];
#pragma unroll
        for (int mi = 0; mi < 2; mi++)
#pragma unroll
            for (int ni = 0; ni < 2; ni++)
#pragma unroll
                for (int q = 0; q < 4; q++) accA[mi][ni][q] = 0.f;

#pragma unroll
        for (int c = 0; c < 4; c++) {
            __syncthreads();
#pragma unroll
            for (int j = 0; j < 2; j++) {
                int idx = tid + j * 512;     // 0..1023 uint4 units
                int mm = idx >> 5, q = idx & 31;
                *(uint4*)(sm + SM_HHI + mm * (RSH * 2) + q * 16) =
                    __ldcg((const uint4*)(g_hhi + mm * HH + c * 256 + q * 8));
                *(uint4*)(sm + SM_HLO + mm * (RSH * 2) + q * 16) =
                    __ldcg((const uint4*)(g_hlo + mm * HH + c * 256 + q * 8));
            }
            __syncthreads();
            const int kk = wid * 16;          // k within chunk
            const int kg = c * 256 + kk;      // global k (for W)
            uint32_t ahi[2][4], alo[2][4], bh[4], bl[4];
#pragma unroll
            for (int mi = 0; mi < 2; mi++) {
                uint32_t off = (uint32_t)((mi * 16 + a_row_add) * (RSH * 2) +
                                          (kk + a_k_add) * 2);
                ldsm_x4(ahi[mi], sb + SM_HHI + off);
                ldsm_x4(alo[mi], sb + SM_HLO + off);
            }
            {
                uint32_t off = (uint32_t)(b_row_add * (RSW * 2) +
                                          (kg + b_k_add) * 2);
                ldsm_x4(bh, sb + SM_WRUHI + off);
                ldsm_x4(bl, sb + SM_WRULO + off);
            }
#pragma unroll
            for (int mi = 0; mi < 2; mi++)
#pragma unroll
                for (int ni = 0; ni < 2; ni++) {
                    mma16816(accA[mi][ni], ahi[mi], &bh[ni * 2]);
                    mma16816(accA[mi][ni], ahi[mi], &bl[ni * 2]);
                    mma16816(accA[mi][ni], alo[mi], &bh[ni * 2]);
                }
        }
        __syncthreads();
#pragma unroll
        for (int mi = 0; mi < 2; mi++)
#pragma unroll
            for (int ni = 0; ni < 2; ni++)
                *(float4*)(red + (wid * 4 + mi * 2 + ni) * 128 + lane * 4) =
                    make_float4(accA[mi][ni][0], accA[mi][ni][1],
                                accA[mi][ni][2], accA[mi][ni][3]);
        __syncthreads();
        {
            int mi = mA >> 4, rm = mA & 15, ni = nA >> 3;
            int rl = ((rm & 7) << 2) | ((nA & 7) >> 1);
            int rg = ((rm >> 3) << 1) | (nA & 1);
            float s = eA + bAv;
            const float* rp = red + (mi * 2 + ni) * 128 + rl * 4 + rg;
#pragma unroll
            for (int w = 0; w < 16; w++) s += rp[w * 512];
            float p = 1.f / (1.f + __expf(-s));
            if (blk < 64) {              // r gate -> rh split bf16
                float rh = p * hA;
                __nv_bfloat16 hi = __float2bfloat16(rh);
                stg16(&g_rhhi[mA * HH + colA], hi);
                stg16(&g_rhlo[mA * HH + colA],
                      __float2bfloat16(rh - __bfloat162float(hi)));
            } else {                     // u gate
                __stcg(&g_u[mA * HH + (colA - HH)], p);
            }
        }
        // Prefetch phase-B embedding (independent of barrier)
        float eB = 0.f;
        if (tid < 256) eB = Ec[g_items[mB * TT + t] * HH + colB];

        // --- split mid-step barrier: two 64-arrival counters ---
        __syncthreads();
        if (tid == 0) {
            __threadfence();
            if (blk < 64) {
                if (atomicAdd(&g_cnt_rh, 1) == 63) {
                    atomicExch(&g_cnt_rh, 0);
                    __threadfence();
                    g_gen_rh = t + 1;
                }
            } else {
                if (atomicAdd(&g_cnt_u, 1) == 63) {
                    atomicExch(&g_cnt_u, 0);
                    __threadfence();
                    g_gen_u = t + 1;
                }
            }
            while (g_gen_rh <= t) { __nanosleep(32); }
            while (g_gen_u  <= t) { __nanosleep(32); }
            __threadfence();
        }
        __syncthreads();

        // ================= Phase B: candidate + h update =================
        // Hoisted epilogue operands (u now globally visible; h stable).
        float uB = 0.f, hB = 0.f;
        if (tid < 256) {
            uB = __ldcg(&g_u[mB * HH + colB]);
            hB = __ldcg(&g_h[mB * HH + colB]);
        }
        float accB[2][4];
#pragma unroll
        for (int mi = 0; mi < 2; mi++)
#pragma unroll
            for (int q = 0; q < 4; q++) accB[mi][q] = 0.f;

#pragma unroll
        for (int c = 0; c < 4; c++) {
            __syncthreads();
#pragma unroll
            for (int j = 0; j < 2; j++) {
                int idx = tid + j * 512;
                int mm = idx >> 5, q = idx & 31;
                *(uint4*)(sm + SM_HHI + mm * (RSH * 2) + q * 16) =
                    __ldcg((const uint4*)(g_rhhi + mm * HH + c * 256 + q * 8));
                *(uint4*)(sm + SM_HLO + mm * (RSH * 2) + q * 16) =
                    __ldcg((const uint4*)(g_rhlo + mm * HH + c * 256 + q * 8));
            }
            __syncthreads();
            const int kk = wid * 16;
            const int kg = c * 256 + kk;
            uint32_t ahi[2][4], alo[2][4], bh2[2], bl2[2];
#pragma unroll
            for (int mi = 0; mi < 2; mi++) {
                uint32_t off = (uint32_t)((mi * 16 + a_row_add) * (RSH * 2) +
                                          (kk + a_k_add) * 2);
                ldsm_x4(ahi[mi], sb + SM_HHI + off);
                ldsm_x4(alo[mi], sb + SM_HLO + off);
            }
            {
                uint32_t off = (uint32_t)(c_row * (RSW * 2) +
                                          (kg + c_k_add) * 2);
                ldsm_x2(bh2, sb + SM_WCHI + off);
                ldsm_x2(bl2, sb + SM_WCLO + off);
            }
#pragma unroll
            for (int mi = 0; mi < 2; mi++) {
                mma16816(accB[mi], ahi[mi], bh2);
                mma16816(accB[mi], ahi[mi], bl2);
                mma16816(accB[mi], alo[mi], bh2);
            }
        }
        __syncthreads();
#pragma unroll
        for (int mi = 0; mi < 2; mi++)
            *(float4*)(red + (wid * 2 + mi) * 128 + lane * 4) =
                make_float4(accB[mi][0], accB[mi][1], accB[mi][2], accB[mi][3]);
        __syncthreads();
        if (tid < 256) {
            int mi = mB >> 4, rm = mB & 15;
            int rl = ((rm & 7) << 2) | (nB >> 1);
            int rg = ((rm >> 3) << 1) | (nB & 1);
            float s = eB + bBv;
            const float* rp = red + mi * 128 + rl * 4 + rg;
#pragma unroll
            for (int w = 0; w < 16; w++) s += rp[w * 256];
            float cc = tanhf(s);
            float hn = uB * hB + (1.f - uB) * cc;
            __stcg(&g_h[mB * HH + colB], hn);
            __nv_bfloat16 hi = __float2bfloat16(hn);
            __nv_bfloat16 lo = __float2bfloat16(hn - __bfloat162float(hi));
            stg16(&g_hhi[mB * HH + colB], hi);
            stg16(&g_hlo[mB * HH + colB], lo);
            stg16(&g_Shi[(mB * TT + t) * HH + colB], hi);
            stg16(&g_Slo[(mB * TT + t) * HH + colB], lo);
            if (t == TT - 1) hf_out[mB * HH + colB] = hn;  // fused h_final
        }
        gridbar();
    }
}

// ---------------------------------------------------------------------------
__global__ void k_conv_w(const float* __restrict__ Wo) {
    int i = blockIdx.x * blockDim.x + threadIdx.x;
    if (i < NPAD * HH) {
        int n = i >> 10, k = i & 1023;
        float x = (n < VV) ? Wo[k * VV + n] : 0.0f;
        __nv_bfloat16 hi = __float2bfloat16(x);
        g_WThi[n * HH + k] = hi;
        g_WTlo[n * HH + k] = __float2bfloat16(x - __bfloat162float(hi));
    }
}

// ---------------------------------------------------------------------------
// Tensor-core output GEMM (R13 winner, unchanged). C[8192, V] = S @ Wo.
#define RSB 80   // smem row stride bytes (40 bf16)

__global__ __launch_bounds__(256) void k_gemm_tc(float* __restrict__ C) {
    __shared__ __align__(16) char smg[4 * 128 * RSB];   // 40960 B
    const uint32_t sbase = smem_u32(smg);
    const uint32_t sAhi = sbase, sAlo = sbase + 10240;
    const uint32_t sBhi = sbase + 20480, sBlo = sbase + 30720;

    const int tid = threadIdx.x, lane = tid & 31, wid = tid >> 5;
    const int warp_m = wid >> 2, warp_n = wid & 3;   // 2 x 4
    const int mt = blockIdx.x * 128, nt = blockIdx.y * 128;

    float acc[4][4][4];
#pragma unroll
    for (int mi = 0; mi < 4; mi++)
#pragma unroll
        for (int ni = 0; ni < 4; ni++)
#pragma unroll
            for (int q = 0; q < 4; q++) acc[mi][ni][q] = 0.f;

    const int lm_mat = lane >> 3, lm_r = lane & 7;
    const int a_row_add = lm_r + ((lm_mat & 1) << 3);
    const int a_k_add   = (lm_mat >> 1) << 3;
    const int b_row_add = lm_r + ((lm_mat >> 1) << 3);
    const int b_k_add   = (lm_mat & 1) << 3;

    for (int ch = 0; ch < 32; ch++) {
        const int k0 = ch * 32;
        __syncthreads();
#pragma unroll
        for (int j = 0; j < 8; j++) {
            int idx = tid + j * 256;
            int tile = idx >> 9;
            int e = idx & 511;
            int r = e >> 2, q = e & 3;
            char* dst = smg + tile * 10240 + r * RSB + q * 16;
            const __nv_bfloat16* src;
            if (tile == 0)      src = &g_Shi[(mt + r) * HH + k0 + q * 8];
            else if (tile == 1) src = &g_Slo[(mt + r) * HH + k0 + q * 8];
            else if (tile == 2) src = &g_WThi[(nt + r) * HH + k0 + q * 8];
            else                src = &g_WTlo[(nt + r) * HH + k0 + q * 8];
            *(uint4*)dst = *(const uint4*)src;
        }
        __syncthreads();

#pragma unroll
        for (int kk = 0; kk < 32; kk += 16) {
            uint32_t ahi[4][4], alo[4][4], bhi[2][4], blo[2][4];
#pragma unroll
            for (int mi = 0; mi < 4; mi++) {
                int row = warp_m * 64 + mi * 16 + a_row_add;
                uint32_t off = (uint32_t)(row * RSB + (kk + a_k_add) * 2);
                ldsm_x4(ahi[mi], sAhi + off);
                ldsm_x4(alo[mi], sAlo + off);
            }
#pragma unroll
            for (int p = 0; p < 2; p++) {
                int row = warp_n * 32 + p * 16 + b_row_add;
                uint32_t off = (uint32_t)(row * RSB + (kk + b_k_add) * 2);
                ldsm_x4(bhi[p], sBhi + off);
                ldsm_x4(blo[p], sBlo + off);
            }
#pragma unroll
            for (int mi = 0; mi < 4; mi++)
#pragma unroll
                for (int ni = 0; ni < 4; ni++) {
                    const uint32_t* bh = &bhi[ni >> 1][(ni & 1) * 2];
                    const uint32_t* bl = &blo[ni >> 1][(ni & 1) * 2];
                    mma16816(acc[mi][ni], ahi[mi], bh);
                    mma16816(acc[mi][ni], ahi[mi], bl);
                    mma16816(acc[mi][ni], alo[mi], bh);
                }
        }
    }

    const int g = lane >> 2, t2 = (lane & 3) * 2;
#pragma unroll
    for (int mi = 0; mi < 4; mi++) {
#pragma unroll
        for (int ni = 0; ni < 4; ni++) {
            int m0 = mt + warp_m * 64 + mi * 16 + g;
            int n0 = nt + warp_n * 32 + ni * 8 + t2;
            if (n0 < VV) {
                C[m0 * VV + n0] = acc[mi][ni][0];
                C[(m0 + 8) * VV + n0] = acc[mi][ni][2];
            }
            if (n0 + 1 < VV) {
                C[m0 * VV + n0 + 1] = acc[mi][ni][1];
                C[(m0 + 8) * VV + n0 + 1] = acc[mi][ni][3];
            }
        }
    }
}

// ---------------------------------------------------------------------------
extern "C" void kernel_launch(void* const* d_in, const int* in_sizes, int n_in,
                              void* d_out, int out_size)
{
    const int*   items_raw = (const int*)d_in[0];
    const float* h0   = (const float*)d_in[1];
    const float* E_ru = (const float*)d_in[2];
    const float* W_ru = (const float*)d_in[3];
    const float* b_ru = (const float*)d_in[4];
    const float* E_c  = (const float*)d_in[5];
    const float* W_c  = (const float*)d_in[6];
    const float* b_c  = (const float*)d_in[7];
    const float* W_out = (const float*)d_in[8];

    float* out = (float*)d_out;
    float* logits = out + BB * HH;

    cudaFuncSetAttribute(k_rnn, cudaFuncAttributeMaxDynamicSharedMemorySize,
                         SM_TOTAL);

    k_init<<<(BB * HH + 255) / 256, 256>>>(h0);
    k_detect<<<(BB * TT / 2 + 255) / 256, 256>>>(items_raw);
    k_convert<<<(BB * TT + 255) / 256, 256>>>(items_raw);
    k_conv_w<<<(NPAD * HH + 255) / 256, 256>>>(W_out);

    k_rnn<<<NB, 512, SM_TOTAL>>>(E_ru, b_ru, E_c, b_c, W_ru, W_c, out);

    dim3 ggrid((BB * TT) / 128, NPAD / 128);
    k_gemm_tc<<<ggrid, 256>>>(logits);
}

// round 16
// speedup vs baseline: 1.0899x; 1.0335x over previous
#include <cuda_runtime.h>
#include <cuda_bf16.h>
#include <cstdint>

// CollaborativeRNN (GRU-like): B=32, T=256, H=1024, V=10001
// out = [h_final (B*H) | logits (B*T*V)]  (float32)

#define BB 32
#define TT 256
#define HH 1024
#define H2 2048
#define VV 10001
#define NB 128
#define NPAD 10112  // 79 * 128

typedef unsigned long long u64;

// State (row-major [b][k]) and scratch
__device__ float g_h[BB * HH];
__device__ float g_u[BB * HH];
__device__ __align__(16) __nv_bfloat16 g_hhi[BB * HH];
__device__ __align__(16) __nv_bfloat16 g_hlo[BB * HH];
__device__ __align__(16) __nv_bfloat16 g_rhhi[BB * HH];
__device__ __align__(16) __nv_bfloat16 g_rhlo[BB * HH];
__device__ int   g_items[BB * TT];
__device__ int   g_nzodd;
__device__ int   g_count;
__device__ volatile int g_gen;
__device__ int   g_cnt_rh;
__device__ int   g_cnt_u;
__device__ volatile int g_gen_rh;
__device__ volatile int g_gen_u;
__device__ __align__(16) __nv_bfloat16 g_Shi[BB * TT * HH];
__device__ __align__(16) __nv_bfloat16 g_Slo[BB * TT * HH];
__device__ __align__(16) __nv_bfloat16 g_WThi[NPAD * HH];   // W_out^T [n][k]
__device__ __align__(16) __nv_bfloat16 g_WTlo[NPAD * HH];

__device__ __forceinline__ uint32_t smem_u32(const void* p) {
    uint32_t a;
    asm("{ .reg .u64 t; cvta.to.shared.u64 t, %1; cvt.u32.u64 %0, t; }"
        : "=r"(a) : "l"(p));
    return a;
}
__device__ __forceinline__ void ldsm_x4(uint32_t* r, uint32_t addr) {
    asm volatile("ldmatrix.sync.aligned.m8n8.x4.shared.b16 {%0,%1,%2,%3}, [%4];"
                 : "=r"(r[0]), "=r"(r[1]), "=r"(r[2]), "=r"(r[3]) : "r"(addr));
}
__device__ __forceinline__ void ldsm_x2(uint32_t* r, uint32_t addr) {
    asm volatile("ldmatrix.sync.aligned.m8n8.x2.shared.b16 {%0,%1}, [%2];"
                 : "=r"(r[0]), "=r"(r[1]) : "r"(addr));
}
__device__ __forceinline__ void mma16816(float* c, const uint32_t* a,
                                         const uint32_t* b) {
    asm volatile(
        "mma.sync.aligned.m16n8k16.row.col.f32.bf16.bf16.f32 "
        "{%0,%1,%2,%3}, {%4,%5,%6,%7}, {%8,%9}, {%0,%1,%2,%3};"
        : "+f"(c[0]), "+f"(c[1]), "+f"(c[2]), "+f"(c[3])
        : "r"(a[0]), "r"(a[1]), "r"(a[2]), "r"(a[3]), "r"(b[0]), "r"(b[1]));
}
__device__ __forceinline__ void stg16(__nv_bfloat16* p, __nv_bfloat16 v) {
    unsigned short u = *(unsigned short*)&v;
    asm volatile("st.global.cg.u16 [%0], %1;" :: "l"(p), "h"(u));
}

// ---------------------------------------------------------------------------
__global__ void k_init(const float* __restrict__ h0) {
    int i = blockIdx.x * blockDim.x + threadIdx.x;
    if (i == 0) {
        g_nzodd = 0; g_count = 0; g_gen = 0;
        g_cnt_rh = 0; g_cnt_u = 0; g_gen_rh = 0; g_gen_u = 0;
    }
    if (i < BB * HH) {
        float x = h0[i];
        g_h[i] = x;
        __nv_bfloat16 hi = __float2bfloat16(x);
        g_hhi[i] = hi;
        g_hlo[i] = __float2bfloat16(x - __bfloat162float(hi));
    }
}
__global__ void k_detect(const int* __restrict__ w) {
    int i = blockIdx.x * blockDim.x + threadIdx.x;
    if (i < (BB * TT) / 2) {
        if (w[2 * i + 1] != 0) atomicOr(&g_nzodd, 1);
    }
}
__global__ void k_convert(const int* __restrict__ w) {
    int i = blockIdx.x * blockDim.x + threadIdx.x;
    if (i < BB * TT) g_items[i] = g_nzodd ? w[i] : w[2 * i];
}

// ---------------------------------------------------------------------------
__device__ __forceinline__ void gridbar() {
    __syncthreads();
    if (threadIdx.x == 0) {
        __threadfence();
        int gen = g_gen;
        if (atomicAdd(&g_count, 1) == NB - 1) {
            atomicExch(&g_count, 0);
            __threadfence();
            g_gen = gen + 1;
        } else {
            while (g_gen == gen) { __nanosleep(32); }
            __threadfence();
        }
    }
    __syncthreads();
}

// ---------------------------------------------------------------------------
// Tensor-core persistent recurrence; double-buffered register-pipelined
// staging (2 x 33 KB buffers, 1 sync per chunk). 128 blocks x 512 threads.
#define RSW 1032   // W row stride (bf16 elements)
#define RSH 264    // h stage row stride (bf16 elements); 528 B
#define SM_WRUHI 0
#define SM_WRULO 33024
#define SM_WCHI  66048
#define SM_WCLO  82560
#define SM_STG   99072     // 2 buffers x 33792 B (hi at +0, lo at +16896)
#define STGSZ    33792
#define SM_RED   166656    // 32768 B
#define SM_TOTAL 199424

__global__ __launch_bounds__(512) void k_rnn(
    const float* __restrict__ Eru, const float* __restrict__ bru,
    const float* __restrict__ Ec,  const float* __restrict__ bc,
    const float* __restrict__ Wru, const float* __restrict__ Wc,
    float* __restrict__ hf_out)
{
    extern __shared__ char sm[];
    const uint32_t sb = smem_u32(sm);
    float* red = (float*)(sm + SM_RED);

    const int tid  = threadIdx.x;
    const int lane = tid & 31;
    const int wid  = tid >> 5;
    const int blk  = blockIdx.x;

    // One-time weight load + split conversion into smem
    for (int j = 0; j < 32; j++) {
        int i = tid + j * 512;               // 0..16383
        int n = i & 15, k = i >> 4;
        float x = Wru[k * H2 + blk * 16 + n];
        __nv_bfloat16 hi = __float2bfloat16(x);
        *(__nv_bfloat16*)(sm + SM_WRUHI + (n * RSW + k) * 2) = hi;
        *(__nv_bfloat16*)(sm + SM_WRULO + (n * RSW + k) * 2) =
            __float2bfloat16(x - __bfloat162float(hi));
    }
    for (int j = 0; j < 16; j++) {
        int i = tid + j * 512;               // 0..8191
        int n = i & 7, k = i >> 3;
        float x = Wc[k * HH + blk * 8 + n];
        __nv_bfloat16 hi = __float2bfloat16(x);
        *(__nv_bfloat16*)(sm + SM_WCHI + (n * RSW + k) * 2) = hi;
        *(__nv_bfloat16*)(sm + SM_WCLO + (n * RSW + k) * 2) =
            __float2bfloat16(x - __bfloat162float(hi));
    }

    // Output roles
    const int mA = tid >> 4, nA = tid & 15;       // phase A (512 outputs)
    const int colA = blk * 16 + nA;
    const float bAv = bru[colA];
    const int mB = tid >> 3, nB = tid & 7;        // phase B (256 outputs)
    const int colB = blk * 8 + nB;
    const float bBv = (tid < 256) ? bc[colB] : 0.f;

    // ldmatrix lane addressing (validated mapping)
    const int lm_mat = lane >> 3, lm_r = lane & 7;
    const int a_row_add = lm_r + ((lm_mat & 1) << 3);
    const int a_k_add   = (lm_mat >> 1) << 3;
    const int b_row_add = lm_r + ((lm_mat >> 1) << 3);
    const int b_k_add   = (lm_mat & 1) << 3;
    const int l16 = lane & 15;
    const int c_row = l16 & 7, c_k_add = (l16 >> 3) << 3;

    // Staging thread map: thread covers uint4 idx {tid, tid+512}
    const int mm0 = tid >> 5, q0 = tid & 31;       // rows 0..15
    const int mm1 = mm0 + 16;                      // rows 16..31

    __syncthreads();

    for (int t = 0; t < TT; t++) {
        // ================= Phase A: ru gates =================
        float eA = Eru[g_items[mA * TT + t] * H2 + colA];
        float hA = 0.f;
        if (blk < 64) hA = __ldcg(&g_h[mA * HH + colA]);

        float accA[2][2][4];
#pragma unroll
        for (int mi = 0; mi < 2; mi++)
#pragma unroll
            for (int ni = 0; ni < 2; ni++)
#pragma unroll
                for (int q = 0; q < 4; q++) accA[mi][ni][q] = 0.f;

        {
            uint4 rh0, rl0, rh1, rl1;
            rh0 = __ldcg((const uint4*)(g_hhi + mm0 * HH + q0 * 8));
            rl0 = __ldcg((const uint4*)(g_hlo + mm0 * HH + q0 * 8));
            rh1 = __ldcg((const uint4*)(g_hhi + mm1 * HH + q0 * 8));
            rl1 = __ldcg((const uint4*)(g_hlo + mm1 * HH + q0 * 8));
#pragma unroll
            for (int c = 0; c < 4; c++) {
                char* buf = sm + SM_STG + (c & 1) * STGSZ;
                *(uint4*)(buf + mm0 * (RSH * 2) + q0 * 16) = rh0;
                *(uint4*)(buf + 16896 + mm0 * (RSH * 2) + q0 * 16) = rl0;
                *(uint4*)(buf + mm1 * (RSH * 2) + q0 * 16) = rh1;
                *(uint4*)(buf + 16896 + mm1 * (RSH * 2) + q0 * 16) = rl1;
                __syncthreads();
                if (c < 3) {
                    const int ko = (c + 1) * 256;
                    rh0 = __ldcg((const uint4*)(g_hhi + mm0 * HH + ko + q0 * 8));
                    rl0 = __ldcg((const uint4*)(g_hlo + mm0 * HH + ko + q0 * 8));
                    rh1 = __ldcg((const uint4*)(g_hhi + mm1 * HH + ko + q0 * 8));
                    rl1 = __ldcg((const uint4*)(g_hlo + mm1 * HH + ko + q0 * 8));
                }
                const uint32_t stg = sb + SM_STG + (c & 1) * STGSZ;
                const int kk = wid * 16;          // k within chunk
                const int kg = c * 256 + kk;      // global k (for W)
                uint32_t ahi[2][4], alo[2][4], bh[4], bl[4];
#pragma unroll
                for (int mi = 0; mi < 2; mi++) {
                    uint32_t off = (uint32_t)((mi * 16 + a_row_add) * (RSH * 2) +
                                              (kk + a_k_add) * 2);
                    ldsm_x4(ahi[mi], stg + off);
                    ldsm_x4(alo[mi], stg + 16896 + off);
                }
                {
                    uint32_t off = (uint32_t)(b_row_add * (RSW * 2) +
                                              (kg + b_k_add) * 2);
                    ldsm_x4(bh, sb + SM_WRUHI + off);
                    ldsm_x4(bl, sb + SM_WRULO + off);
                }
#pragma unroll
                for (int mi = 0; mi < 2; mi++)
#pragma unroll
                    for (int ni = 0; ni < 2; ni++) {
                        mma16816(accA[mi][ni], ahi[mi], &bh[ni * 2]);
                        mma16816(accA[mi][ni], ahi[mi], &bl[ni * 2]);
                        mma16816(accA[mi][ni], alo[mi], &bh[ni * 2]);
                    }
            }
        }
        // reduction (red region disjoint from stage; no pre-sync needed)
#pragma unroll
        for (int mi = 0; mi < 2; mi++)
#pragma unroll
            for (int ni = 0; ni < 2; ni++)
                *(float4*)(red + (wid * 4 + mi * 2 + ni) * 128 + lane * 4) =
                    make_float4(accA[mi][ni][0], accA[mi][ni][1],
                                accA[mi][ni][2], accA[mi][ni][3]);
        __syncthreads();
        {
            int mi = mA >> 4, rm = mA & 15, ni = nA >> 3;
            int rl = ((rm & 7) << 2) | ((nA & 7) >> 1);
            int rg = ((rm >> 3) << 1) | (nA & 1);
            float s = eA + bAv;
            const float* rp = red + (mi * 2 + ni) * 128 + rl * 4 + rg;
#pragma unroll
            for (int w = 0; w < 16; w++) s += rp[w * 512];
            float p = 1.f / (1.f + __expf(-s));
            if (blk < 64) {              // r gate -> rh split bf16
                float rh = p * hA;
                __nv_bfloat16 hi = __float2bfloat16(rh);
                stg16(&g_rhhi[mA * HH + colA], hi);
                stg16(&g_rhlo[mA * HH + colA],
                      __float2bfloat16(rh - __bfloat162float(hi)));
            } else {                     // u gate
                __stcg(&g_u[mA * HH + (colA - HH)], p);
            }
        }
        float eB = 0.f;
        if (tid < 256) eB = Ec[g_items[mB * TT + t] * HH + colB];

        // --- split mid-step barrier: two 64-arrival counters ---
        __syncthreads();
        if (tid == 0) {
            __threadfence();
            if (blk < 64) {
                if (atomicAdd(&g_cnt_rh, 1) == 63) {
                    atomicExch(&g_cnt_rh, 0);
                    __threadfence();
                    g_gen_rh = t + 1;
                }
            } else {
                if (atomicAdd(&g_cnt_u, 1) == 63) {
                    atomicExch(&g_cnt_u, 0);
                    __threadfence();
                    g_gen_u = t + 1;
                }
            }
            while (g_gen_rh <= t) { __nanosleep(32); }
            while (g_gen_u  <= t) { __nanosleep(32); }
            __threadfence();
        }
        __syncthreads();

        // ================= Phase B: candidate + h update =================
        float uB = 0.f, hB = 0.f;
        if (tid < 256) {
            uB = __ldcg(&g_u[mB * HH + colB]);
            hB = __ldcg(&g_h[mB * HH + colB]);
        }
        float accB[2][4];
#pragma unroll
        for (int mi = 0; mi < 2; mi++)
#pragma unroll
            for (int q = 0; q < 4; q++) accB[mi][q] = 0.f;

        {
            uint4 rh0, rl0, rh1, rl1;
            rh0 = __ldcg((const uint4*)(g_rhhi + mm0 * HH + q0 * 8));
            rl0 = __ldcg((const uint4*)(g_rhlo + mm0 * HH + q0 * 8));
            rh1 = __ldcg((const uint4*)(g_rhhi + mm1 * HH + q0 * 8));
            rl1 = __ldcg((const uint4*)(g_rhlo + mm1 * HH + q0 * 8));
#pragma unroll
            for (int c = 0; c < 4; c++) {
                char* buf = sm + SM_STG + (c & 1) * STGSZ;
                *(uint4*)(buf + mm0 * (RSH * 2) + q0 * 16) = rh0;
                *(uint4*)(buf + 16896 + mm0 * (RSH * 2) + q0 * 16) = rl0;
                *(uint4*)(buf + mm1 * (RSH * 2) + q0 * 16) = rh1;
                *(uint4*)(buf + 16896 + mm1 * (RSH * 2) + q0 * 16) = rl1;
                __syncthreads();
                if (c < 3) {
                    const int ko = (c + 1) * 256;
                    rh0 = __ldcg((const uint4*)(g_rhhi + mm0 * HH + ko + q0 * 8));
                    rl0 = __ldcg((const uint4*)(g_rhlo + mm0 * HH + ko + q0 * 8));
                    rh1 = __ldcg((const uint4*)(g_rhhi + mm1 * HH + ko + q0 * 8));
                    rl1 = __ldcg((const uint4*)(g_rhlo + mm1 * HH + ko + q0 * 8));
                }
                const uint32_t stg = sb + SM_STG + (c & 1) * STGSZ;
                const int kk = wid * 16;
                const int kg = c * 256 + kk;
                uint32_t ahi[2][4], alo[2][4], bh2[2], bl2[2];
#pragma unroll
                for (int mi = 0; mi < 2; mi++) {
                    uint32_t off = (uint32_t)((mi * 16 + a_row_add) * (RSH * 2) +
                                              (kk + a_k_add) * 2);
                    ldsm_x4(ahi[mi], stg + off);
                    ldsm_x4(alo[mi], stg + 16896 + off);
                }
                {
                    uint32_t off = (uint32_t)(c_row * (RSW * 2) +
                                              (kg + c_k_add) * 2);
                    ldsm_x2(bh2, sb + SM_WCHI + off);
                    ldsm_x2(bl2, sb + SM_WCLO + off);
                }
#pragma unroll
                for (int mi = 0; mi < 2; mi++) {
                    mma16816(accB[mi], ahi[mi], bh2);
                    mma16816(accB[mi], ahi[mi], bl2);
                    mma16816(accB[mi], alo[mi], bh2);
                }
            }
        }
#pragma unroll
        for (int mi = 0; mi < 2; mi++)
            *(float4*)(red + (wid * 2 + mi) * 128 + lane * 4) =
                make_float4(accB[mi][0], accB[mi][1], accB[mi][2], accB[mi][3]);
        __syncthreads();
        if (tid < 256) {
            int mi = mB >> 4, rm = mB & 15;
            int rl = ((rm & 7) << 2) | (nB >> 1);
            int rg = ((rm >> 3) << 1) | (nB & 1);
            float s = eB + bBv;
            const float* rp = red + mi * 128 + rl * 4 + rg;
#pragma unroll
            for (int w = 0; w < 16; w++) s += rp[w * 256];
            float cc = tanhf(s);
            float hn = uB * hB + (1.f - uB) * cc;
            __stcg(&g_h[mB * HH + colB], hn);
            __nv_bfloat16 hi = __float2bfloat16(hn);
            __nv_bfloat16 lo = __float2bfloat16(hn - __bfloat162float(hi));
            stg16(&g_hhi[mB * HH + colB], hi);
            stg16(&g_hlo[mB * HH + colB], lo);
            stg16(&g_Shi[(mB * TT + t) * HH + colB], hi);
            stg16(&g_Slo[(mB * TT + t) * HH + colB], lo);
            if (t == TT - 1) hf_out[mB * HH + colB] = hn;  // fused h_final
        }
        gridbar();
    }
}

// ---------------------------------------------------------------------------
__global__ void k_conv_w(const float* __restrict__ Wo) {
    int i = blockIdx.x * blockDim.x + threadIdx.x;
    if (i < NPAD * HH) {
        int n = i >> 10, k = i & 1023;
        float x = (n < VV) ? Wo[k * VV + n] : 0.0f;
        __nv_bfloat16 hi = __float2bfloat16(x);
        g_WThi[n * HH + k] = hi;
        g_WTlo[n * HH + k] = __float2bfloat16(x - __bfloat162float(hi));
    }
}

// ---------------------------------------------------------------------------
// Tensor-core output GEMM (R13 winner, unchanged — static 40KB smem keeps
// multi-block residency for latency hiding). C[8192, V] = S @ Wo.
#define RSB 80   // smem row stride bytes (40 bf16)

__global__ __launch_bounds__(256) void k_gemm_tc(float* __restrict__ C) {
    __shared__ __align__(16) char smg[4 * 128 * RSB];   // 40960 B
    const uint32_t sbase = smem_u32(smg);
    const uint32_t sAhi = sbase, sAlo = sbase + 10240;
    const uint32_t sBhi = sbase + 20480, sBlo = sbase + 30720;

    const int tid = threadIdx.x, lane = tid & 31, wid = tid >> 5;
    const int warp_m = wid >> 2, warp_n = wid & 3;   // 2 x 4
    const int mt = blockIdx.x * 128, nt = blockIdx.y * 128;

    float acc[4][4][4];
#pragma unroll
    for (int mi = 0; mi < 4; mi++)
#pragma unroll
        for (int ni = 0; ni < 4; ni++)
#pragma unroll
            for (int q = 0; q < 4; q++) acc[mi][ni][q] = 0.f;

    const int lm_mat = lane >> 3, lm_r = lane & 7;
    const int a_row_add = lm_r + ((lm_mat & 1) << 3);
    const int a_k_add   = (lm_mat >> 1) << 3;
    const int b_row_add = lm_r + ((lm_mat >> 1) << 3);
    const int b_k_add   = (lm_mat & 1) << 3;

    for (int ch = 0; ch < 32; ch++) {
        const int k0 = ch * 32;
        __syncthreads();
#pragma unroll
        for (int j = 0; j < 8; j++) {
            int idx = tid + j * 256;
            int tile = idx >> 9;
            int e = idx & 511;
            int r = e >> 2, q = e & 3;
            char* dst = smg + tile * 10240 + r * RSB + q * 16;
            const __nv_bfloat16* src;
            if (tile == 0)      src = &g_Shi[(mt + r) * HH + k0 + q * 8];
            else if (tile == 1) src = &g_Slo[(mt + r) * HH + k0 + q * 8];
            else if (tile == 2) src = &g_WThi[(nt + r) * HH + k0 + q * 8];
            else                src = &g_WTlo[(nt + r) * HH + k0 + q * 8];
            *(uint4*)dst = *(const uint4*)src;
        }
        __syncthreads();

#pragma unroll
        for (int kk = 0; kk < 32; kk += 16) {
            uint32_t ahi[4][4], alo[4][4], bhi[2][4], blo[2][4];
#pragma unroll
            for (int mi = 0; mi < 4; mi++) {
                int row = warp_m * 64 + mi * 16 + a_row_add;
                uint32_t off = (uint32_t)(row * RSB + (kk + a_k_add) * 2);
                ldsm_x4(ahi[mi], sAhi + off);
                ldsm_x4(alo[mi], sAlo + off);
            }
#pragma unroll
            for (int p = 0; p < 2; p++) {
                int row = warp_n * 32 + p * 16 + b_row_add;
                uint32_t off = (uint32_t)(row * RSB + (kk + b_k_add) * 2);
                ldsm_x4(bhi[p], sBhi + off);
                ldsm_x4(blo[p], sBlo + off);
            }
#pragma unroll
            for (int mi = 0; mi < 4; mi++)
#pragma unroll
                for (int ni = 0; ni < 4; ni++) {
                    const uint32_t* bh = &bhi[ni >> 1][(ni & 1) * 2];
                    const uint32_t* bl = &blo[ni >> 1][(ni & 1) * 2];
                    mma16816(acc[mi][ni], ahi[mi], bh);
                    mma16816(acc[mi][ni], ahi[mi], bl);
                    mma16816(acc[mi][ni], alo[mi], bh);
                }
        }
    }

    const int g = lane >> 2, t2 = (lane & 3) * 2;
#pragma unroll
    for (int mi = 0; mi < 4; mi++) {
#pragma unroll
        for (int ni = 0; ni < 4; ni++) {
            int m0 = mt + warp_m * 64 + mi * 16 + g;
            int n0 = nt + warp_n * 32 + ni * 8 + t2;
            if (n0 < VV) {
                C[m0 * VV + n0] = acc[mi][ni][0];
                C[(m0 + 8) * VV + n0] = acc[mi][ni][2];
            }
            if (n0 + 1 < VV) {
                C[m0 * VV + n0 + 1] = acc[mi][ni][1];
                C[(m0 + 8) * VV + n0 + 1] = acc[mi][ni][3];
            }
        }
    }
}

// ---------------------------------------------------------------------------
extern "C" void kernel_launch(void* const* d_in, const int* in_sizes, int n_in,
                              void* d_out, int out_size)
{
    const int*   items_raw = (const int*)d_in[0];
    const float* h0   = (const float*)d_in[1];
    const float* E_ru = (const float*)d_in[2];
    const float* W_ru = (const float*)d_in[3];
    const float* b_ru = (const float*)d_in[4];
    const float* E_c  = (const float*)d_in[5];
    const float* W_c  = (const float*)d_in[6];
    const float* b_c  = (const float*)d_in[7];
    const float* W_out = (const float*)d_in[8];

    float* out = (float*)d_out;
    float* logits = out + BB * HH;

    cudaFuncSetAttribute(k_rnn, cudaFuncAttributeMaxDynamicSharedMemorySize,
                         SM_TOTAL);

    k_init<<<(BB * HH + 255) / 256, 256>>>(h0);
    k_detect<<<(BB * TT / 2 + 255) / 256, 256>>>(items_raw);
    k_convert<<<(BB * TT + 255) / 256, 256>>>(items_raw);
    k_conv_w<<<(NPAD * HH + 255) / 256, 256>>>(W_out);

    k_rnn<<<NB, 512, SM_TOTAL>>>(E_ru, b_ru, E_c, b_c, W_ru, W_c, out);

    dim3 ggrid((BB * TT) / 128, NPAD / 128);
    k_gemm_tc<<<ggrid, 256>>>(logits);
}